// round 1
// baseline (speedup 1.0000x reference)
#include <cuda_runtime.h>
#include <math.h>

// Problem caps (actual sizes taken from in_sizes at launch)
#define N_CAP 50048
#define E_CAP 500224

// ---------------- scratch (device globals; no allocation allowed) ----------
__device__ float g_xl[N_CAP * 64];        // per-layer lin_l output (stride 64/32/16)
__device__ float g_xr[N_CAP * 64];        // per-layer lin_r output
__device__ float g_m1[N_CAP * 4];
__device__ float g_s1[N_CAP * 4];
__device__ float g_num1[N_CAP * 64];
__device__ float g_m2[N_CAP * 2];
__device__ float g_s2[N_CAP * 2];
__device__ float g_num2[N_CAP * 32];
__device__ float g_m3[N_CAP];
__device__ float g_s3[N_CAP];
__device__ float g_num3[N_CAP * 16];
__device__ float g_logits[E_CAP * 4];     // reused per layer (stride 4/2/1)
__device__ float g_ea23[E_CAP * 48];      // staged edge projections for layers 2+3
__device__ float g_x3[N_CAP * 16];

// ---------------- helpers ---------------------------------------------------
__device__ __forceinline__ float leakyr(float v) { return v > 0.f ? v : 0.2f * v; }
__device__ __forceinline__ float eluf(float v)   { return v > 0.f ? v : (expf(v) - 1.f); }

__device__ __forceinline__ void atomicMaxF(float* a, float v) {
    if (v >= 0.f) atomicMax(reinterpret_cast<int*>(a), __float_as_int(v));
    else          atomicMin(reinterpret_cast<unsigned int*>(a), __float_as_uint(v));
}

// ---------------- layer 1 node projection + init ---------------------------
// grid = n blocks, 64 threads. x = node_emb[node_ids[n]] (32) -> xl1,xr1 (64 each)
__global__ void k_node1(const int* __restrict__ node_ids,
                        const float* __restrict__ emb,
                        const float* __restrict__ Wl, const float* __restrict__ bl,
                        const float* __restrict__ Wr, const float* __restrict__ br,
                        int n) {
    int node = blockIdx.x;
    if (node >= n) return;
    int c = threadIdx.x;  // 0..63
    __shared__ float sx[32];
    if (c < 32) sx[c] = emb[node_ids[node] * 32 + c];
    __syncthreads();
    float al = bl[c], ar = br[c];
#pragma unroll
    for (int k = 0; k < 32; k++) {
        float xv = sx[k];
        al += xv * Wl[k * 64 + c];
        ar += xv * Wr[k * 64 + c];
    }
    g_xl[node * 64 + c] = al;
    g_xr[node * 64 + c] = ar;
    g_num1[node * 64 + c] = 0.f;
    if (c < 4) { g_m1[node * 4 + c] = -INFINITY; g_s1[node * 4 + c] = 0.f; }
}

// ---------------- fused edge projection (all 3 layers) + layer-1 logits -----
// Block = 128 threads = 4 warps = 4 edges. Each warp: lane j<16 -> 4 cols of
// ea1 (64), j 16..23 -> 4 cols of ea2 (32), j 24..27 -> 4 cols of ea3 (16).
__global__ void k_edge_proj(const float* __restrict__ eattr,
                            const int* __restrict__ src, const int* __restrict__ dst,
                            const float* __restrict__ We1, const float* __restrict__ We2,
                            const float* __restrict__ We3, const float* __restrict__ att1,
                            int e) {
    __shared__ float sa[4][385];
    int eb = blockIdx.x * 4;
    for (int idx = threadIdx.x; idx < 4 * 385; idx += 128) {
        int w = idx / 385, d = idx - w * 385;
        int ee = eb + w;
        if (ee < e) sa[w][d] = eattr[ee * 385 + d];
    }
    __syncthreads();

    int w = threadIdx.x >> 5, j = threadIdx.x & 31;
    int ee = eb + w;
    if (ee >= e) return;

    const float* Wp; int ld, col;
    if (j < 16)      { Wp = We1; ld = 64; col = j * 4; }
    else if (j < 24) { Wp = We2; ld = 32; col = (j - 16) * 4; }
    else if (j < 28) { Wp = We3; ld = 16; col = (j - 24) * 4; }
    else             { Wp = We1; ld = 64; col = 0; }   // idle lanes, safe addr

    float4 acc = make_float4(0.f, 0.f, 0.f, 0.f);
    const float* arow = sa[w];
#pragma unroll 5
    for (int d = 0; d < 385; d++) {
        float a = arow[d];
        float4 wv = *reinterpret_cast<const float4*>(Wp + d * ld + col);
        acc.x += a * wv.x; acc.y += a * wv.y;
        acc.z += a * wv.z; acc.w += a * wv.w;
    }

    int s = src[ee], t = dst[ee];
    if (j < 16) {
        float4 xj = *reinterpret_cast<const float4*>(g_xl + s * 64 + col);
        float4 xi = *reinterpret_cast<const float4*>(g_xr + t * 64 + col);
        float p = leakyr(xj.x + xi.x + acc.x) * att1[col]
                + leakyr(xj.y + xi.y + acc.y) * att1[col + 1]
                + leakyr(xj.z + xi.z + acc.z) * att1[col + 2]
                + leakyr(xj.w + xi.w + acc.w) * att1[col + 3];
        p += __shfl_xor_sync(0x0000FFFFu, p, 1);
        p += __shfl_xor_sync(0x0000FFFFu, p, 2);
        if ((j & 3) == 0) {
            int h = j >> 2;
            g_logits[ee * 4 + h] = p;
            atomicMaxF(&g_m1[t * 4 + h], p);
        }
    } else if (j < 28) {
        int off = (j < 24) ? (j - 16) * 4 : 32 + (j - 24) * 4;
        *reinterpret_cast<float4*>(g_ea23 + ee * 48 + off) = acc;
    }
}

// ---------------- softmax-exp + weighted aggregation (per layer) -----------
__global__ void k_soft1(const int* __restrict__ src, const int* __restrict__ dst, int e) {
    int t = blockIdx.x * blockDim.x + threadIdx.x;
    int ee = t >> 6;
    if (ee >= e) return;
    int idx = t & 63, h = idx >> 4;
    int s = src[ee], d = dst[ee];
    float ex = expf(g_logits[ee * 4 + h] - g_m1[d * 4 + h]);
    if ((idx & 15) == 0) atomicAdd(&g_s1[d * 4 + h], ex);
    atomicAdd(&g_num1[d * 64 + idx], ex * g_xl[s * 64 + idx]);
}

__global__ void k_soft2(const int* __restrict__ src, const int* __restrict__ dst, int e) {
    int t = blockIdx.x * blockDim.x + threadIdx.x;
    int ee = t >> 5;
    if (ee >= e) return;
    int idx = t & 31, h = idx >> 4;
    int s = src[ee], d = dst[ee];
    float ex = expf(g_logits[ee * 2 + h] - g_m2[d * 2 + h]);
    if ((idx & 15) == 0) atomicAdd(&g_s2[d * 2 + h], ex);
    atomicAdd(&g_num2[d * 32 + idx], ex * g_xl[s * 32 + idx]);
}

__global__ void k_soft3(const int* __restrict__ src, const int* __restrict__ dst, int e) {
    int t = blockIdx.x * blockDim.x + threadIdx.x;
    int ee = t >> 4;
    if (ee >= e) return;
    int idx = t & 15;
    int s = src[ee], d = dst[ee];
    float ex = expf(g_logits[ee] - g_m3[d]);
    if (idx == 0) atomicAdd(&g_s3[d], ex);
    atomicAdd(&g_num3[d * 16 + idx], ex * g_xl[s * 16 + idx]);
}

// ---------------- finish layer1 (div,bias,ELU) + project layer2 ------------
__global__ void k_node_fin1(const float* __restrict__ bias1,
                            const float* __restrict__ Wl2, const float* __restrict__ bl2,
                            const float* __restrict__ Wr2, const float* __restrict__ br2,
                            int n) {
    int node = blockIdx.x;
    if (node >= n) return;
    int c = threadIdx.x;  // 0..63
    __shared__ float sx[64];
    float v = g_num1[node * 64 + c] / (g_s1[node * 4 + (c >> 4)] + 1e-16f) + bias1[c];
    sx[c] = eluf(v);
    __syncthreads();
    if (c < 32) {
        float a = bl2[c];
#pragma unroll
        for (int k = 0; k < 64; k++) a += sx[k] * Wl2[k * 32 + c];
        g_xl[node * 32 + c] = a;
        g_num2[node * 32 + c] = 0.f;
    } else {
        int c2 = c - 32;
        float a = br2[c2];
#pragma unroll
        for (int k = 0; k < 64; k++) a += sx[k] * Wr2[k * 32 + c2];
        g_xr[node * 32 + c2] = a;
    }
    if (c < 2) { g_m2[node * 2 + c] = -INFINITY; g_s2[node * 2 + c] = 0.f; }
}

// ---------------- layer-2 logits --------------------------------------------
__global__ void k_edge_logits2(const int* __restrict__ src, const int* __restrict__ dst,
                               const float* __restrict__ att2, int e) {
    int ee = blockIdx.x * 8 + (threadIdx.x >> 5);
    if (ee >= e) return;  // whole warp exits together
    int c = threadIdx.x & 31;
    int s = src[ee], d = dst[ee];
    float ev = leakyr(g_xl[s * 32 + c] + g_xr[d * 32 + c] + g_ea23[ee * 48 + c]);
    float p = ev * att2[c];
    p += __shfl_xor_sync(0xFFFFFFFFu, p, 8);
    p += __shfl_xor_sync(0xFFFFFFFFu, p, 4);
    p += __shfl_xor_sync(0xFFFFFFFFu, p, 2);
    p += __shfl_xor_sync(0xFFFFFFFFu, p, 1);
    if ((c & 15) == 0) {
        int h = c >> 4;
        g_logits[ee * 2 + h] = p;
        atomicMaxF(&g_m2[d * 2 + h], p);
    }
}

// ---------------- finish layer2 + project layer3 ----------------------------
__global__ void k_node_fin2(const float* __restrict__ bias2,
                            const float* __restrict__ Wl3, const float* __restrict__ bl3,
                            const float* __restrict__ Wr3, const float* __restrict__ br3,
                            int n) {
    int node = blockIdx.x;
    if (node >= n) return;
    int c = threadIdx.x;  // 0..31
    __shared__ float sx[32];
    float v = g_num2[node * 32 + c] / (g_s2[node * 2 + (c >> 4)] + 1e-16f) + bias2[c];
    sx[c] = eluf(v);
    __syncthreads();
    if (c < 16) {
        float a = bl3[c];
#pragma unroll
        for (int k = 0; k < 32; k++) a += sx[k] * Wl3[k * 16 + c];
        g_xl[node * 16 + c] = a;
        g_num3[node * 16 + c] = 0.f;
    } else {
        int c2 = c - 16;
        float a = br3[c2];
#pragma unroll
        for (int k = 0; k < 32; k++) a += sx[k] * Wr3[k * 16 + c2];
        g_xr[node * 16 + c2] = a;
    }
    if (c == 0) { g_m3[node] = -INFINITY; g_s3[node] = 0.f; }
}

// ---------------- layer-3 logits (16 lanes per edge, 8 edges / 128 thr) -----
__global__ void k_edge_logits3(const int* __restrict__ src, const int* __restrict__ dst,
                               const float* __restrict__ att3, int e) {
    int ee = blockIdx.x * 8 + (threadIdx.x >> 4);
    int c = threadIdx.x & 15;
    bool ok = ee < e;
    int s = ok ? src[ee] : 0, d = ok ? dst[ee] : 0;
    float ev = ok ? leakyr(g_xl[s * 16 + c] + g_xr[d * 16 + c] + g_ea23[ee * 48 + 32 + c]) : 0.f;
    float p = ev * att3[c];
    p += __shfl_xor_sync(0xFFFFFFFFu, p, 8);
    p += __shfl_xor_sync(0xFFFFFFFFu, p, 4);
    p += __shfl_xor_sync(0xFFFFFFFFu, p, 2);
    p += __shfl_xor_sync(0xFFFFFFFFu, p, 1);
    if (ok && c == 0) {
        g_logits[ee] = p;
        atomicMaxF(&g_m3[d], p);
    }
}

// ---------------- finish layer3 ---------------------------------------------
__global__ void k_node_fin3(const float* __restrict__ bias3, int n) {
    int i = blockIdx.x * blockDim.x + threadIdx.x;
    if (i >= n * 16) return;
    g_x3[i] = g_num3[i] / (g_s3[i >> 4] + 1e-16f) + bias3[i & 15];
}

// ---------------- edge MLP: [x3[src]||x3[dst]] -> 64 -> 32 -> 1 --------------
__global__ void k_mlp(const int* __restrict__ src, const int* __restrict__ dst,
                      const float* __restrict__ W1, const float* __restrict__ b1,
                      const float* __restrict__ W2, const float* __restrict__ b2,
                      const float* __restrict__ W3, const float* __restrict__ b3,
                      float* __restrict__ out, int e) {
    __shared__ float h0[2][32], h1[2][64], h2[2][32];
    int le = threadIdx.x >> 6;      // sub-edge within block
    int j = threadIdx.x & 63;
    int ee = blockIdx.x * 2 + le;
    bool ok = ee < e;
    if (ok && j < 32) {
        int nn = (j < 16) ? src[ee] : dst[ee];
        h0[le][j] = g_x3[nn * 16 + (j & 15)];
    }
    __syncthreads();
    if (ok) {
        float a = b1[j];
#pragma unroll
        for (int k = 0; k < 32; k++) a += h0[le][k] * W1[k * 64 + j];
        h1[le][j] = fmaxf(a, 0.f);
    }
    __syncthreads();
    if (ok && j < 32) {
        float a = b2[j];
#pragma unroll
        for (int k = 0; k < 64; k++) a += h1[le][k] * W2[k * 32 + j];
        h2[le][j] = fmaxf(a, 0.f);
    }
    __syncthreads();
    if (j < 32) {  // threads 0..31 and 64..95: each a full warp
        float p = ok ? h2[le][j] * W3[j] : 0.f;
        p += __shfl_xor_sync(0xFFFFFFFFu, p, 16);
        p += __shfl_xor_sync(0xFFFFFFFFu, p, 8);
        p += __shfl_xor_sync(0xFFFFFFFFu, p, 4);
        p += __shfl_xor_sync(0xFFFFFFFFu, p, 2);
        p += __shfl_xor_sync(0xFFFFFFFFu, p, 1);
        if (ok && j == 0) out[ee] = p + b3[0];
    }
}

// ---------------- launch -----------------------------------------------------
extern "C" void kernel_launch(void* const* d_in, const int* in_sizes, int n_in,
                              void* d_out, int out_size) {
    const int*   node_ids = (const int*)  d_in[0];
    const int*   eidx     = (const int*)  d_in[1];
    const float* eattr    = (const float*)d_in[2];
    const float* emb      = (const float*)d_in[3];
    const float* l1_Wl   = (const float*)d_in[4];
    const float* l1_bl   = (const float*)d_in[5];
    const float* l1_Wr   = (const float*)d_in[6];
    const float* l1_br   = (const float*)d_in[7];
    const float* l1_We   = (const float*)d_in[8];
    const float* l1_att  = (const float*)d_in[9];
    const float* l1_bias = (const float*)d_in[10];
    const float* l2_Wl   = (const float*)d_in[11];
    const float* l2_bl   = (const float*)d_in[12];
    const float* l2_Wr   = (const float*)d_in[13];
    const float* l2_br   = (const float*)d_in[14];
    const float* l2_We   = (const float*)d_in[15];
    const float* l2_att  = (const float*)d_in[16];
    const float* l2_bias = (const float*)d_in[17];
    const float* l3_Wl   = (const float*)d_in[18];
    const float* l3_bl   = (const float*)d_in[19];
    const float* l3_Wr   = (const float*)d_in[20];
    const float* l3_br   = (const float*)d_in[21];
    const float* l3_We   = (const float*)d_in[22];
    const float* l3_att  = (const float*)d_in[23];
    const float* l3_bias = (const float*)d_in[24];
    const float* mlp_W1  = (const float*)d_in[25];
    const float* mlp_b1  = (const float*)d_in[26];
    const float* mlp_W2  = (const float*)d_in[27];
    const float* mlp_b2  = (const float*)d_in[28];
    const float* mlp_W3  = (const float*)d_in[29];
    const float* mlp_b3  = (const float*)d_in[30];

    int n = in_sizes[0];
    int e = in_sizes[1] / 2;
    const int* src = eidx;
    const int* dst = eidx + e;
    float* out = (float*)d_out;

    // ---- layer 1 ----
    k_node1<<<n, 64>>>(node_ids, emb, l1_Wl, l1_bl, l1_Wr, l1_br, n);
    k_edge_proj<<<(e + 3) / 4, 128>>>(eattr, src, dst, l1_We, l2_We, l3_We, l1_att, e);
    {
        long long tt = (long long)e * 64;
        k_soft1<<<(unsigned)((tt + 255) / 256), 256>>>(src, dst, e);
    }
    k_node_fin1<<<n, 64>>>(l1_bias, l2_Wl, l2_bl, l2_Wr, l2_br, n);

    // ---- layer 2 ----
    k_edge_logits2<<<(e + 7) / 8, 256>>>(src, dst, l2_att, e);
    {
        long long tt = (long long)e * 32;
        k_soft2<<<(unsigned)((tt + 255) / 256), 256>>>(src, dst, e);
    }
    k_node_fin2<<<n, 32>>>(l2_bias, l3_Wl, l3_bl, l3_Wr, l3_br, n);

    // ---- layer 3 ----
    k_edge_logits3<<<(e + 7) / 8, 128>>>(src, dst, l3_att, e);
    {
        long long tt = (long long)e * 16;
        k_soft3<<<(unsigned)((tt + 255) / 256), 256>>>(src, dst, e);
    }
    k_node_fin3<<<(n * 16 + 255) / 256, 256>>>(l3_bias, n);

    // ---- edge MLP ----
    k_mlp<<<(e + 1) / 2, 128>>>(src, dst, mlp_W1, mlp_b1, mlp_W2, mlp_b2,
                                mlp_W3, mlp_b3, out, e);
}

// round 2
// speedup vs baseline: 1.9464x; 1.9464x over previous
#include <cuda_runtime.h>
#include <math.h>

#define N_CAP 50048
#define E_CAP 500224

// ---------------- scratch ----------------------------------------------------
__device__ float g_xl[N_CAP * 64];
__device__ float g_xr[N_CAP * 64];
__device__ float g_m1[N_CAP * 4];
__device__ float g_s1[N_CAP * 4];
__device__ float g_num1[N_CAP * 64];
__device__ float g_m2[N_CAP * 2];
__device__ float g_s2[N_CAP * 2];
__device__ float g_num2[N_CAP * 32];
__device__ float g_m3[N_CAP];
__device__ float g_s3[N_CAP];
__device__ float g_num3[N_CAP * 16];
__device__ float g_logits[E_CAP * 4];
__device__ float g_ea23[E_CAP * 48];
__device__ float g_x3[N_CAP * 16];

// ---------------- helpers ----------------------------------------------------
__device__ __forceinline__ float leakyr(float v) { return v > 0.f ? v : 0.2f * v; }
__device__ __forceinline__ float eluf(float v)   { return v > 0.f ? v : (expf(v) - 1.f); }

__device__ __forceinline__ void atomicMaxF(float* a, float v) {
    if (v >= 0.f) atomicMax(reinterpret_cast<int*>(a), __float_as_int(v));
    else          atomicMin(reinterpret_cast<unsigned int*>(a), __float_as_uint(v));
}

__device__ __forceinline__ unsigned long long pack2(float lo, float hi) {
    unsigned long long r;
    asm("mov.b64 %0, {%1, %2};" : "=l"(r) : "f"(lo), "f"(hi));
    return r;
}
__device__ __forceinline__ float2 unpack2(unsigned long long v) {
    float lo, hi;
    asm("mov.b64 {%0, %1}, %2;" : "=f"(lo), "=f"(hi) : "l"(v));
    return make_float2(lo, hi);
}
// packed f32x2 FFMA (HW FFMA2; only reachable via PTX on sm_103a)
__device__ __forceinline__ void fma2(unsigned long long& d,
                                     unsigned long long a, unsigned long long b) {
    asm("fma.rn.f32x2 %0, %1, %2, %3;" : "=l"(d) : "l"(a), "l"(b), "l"(d));
}
// vector atomic add (sm_90+)
__device__ __forceinline__ void red4(float* p, float a, float b, float c, float d) {
    asm volatile("red.global.add.v4.f32 [%0], {%1, %2, %3, %4};"
                 :: "l"(p), "f"(a), "f"(b), "f"(c), "f"(d) : "memory");
}

// ---------------- layer 1 node projection + init ----------------------------
__global__ void k_node1(const int* __restrict__ node_ids,
                        const float* __restrict__ emb,
                        const float* __restrict__ Wl, const float* __restrict__ bl,
                        const float* __restrict__ Wr, const float* __restrict__ br,
                        int n) {
    int node = blockIdx.x;
    if (node >= n) return;
    int c = threadIdx.x;  // 0..63
    __shared__ float sx[32];
    if (c < 32) sx[c] = emb[node_ids[node] * 32 + c];
    __syncthreads();
    float al = bl[c], ar = br[c];
#pragma unroll
    for (int k = 0; k < 32; k++) {
        float xv = sx[k];
        al += xv * Wl[k * 64 + c];
        ar += xv * Wr[k * 64 + c];
    }
    g_xl[node * 64 + c] = al;
    g_xr[node * 64 + c] = ar;
    g_num1[node * 64 + c] = 0.f;
    if (c < 4) { g_m1[node * 4 + c] = -INFINITY; g_s1[node * 4 + c] = 0.f; }
}

// ---------------- fused edge projection (all 3 layers) + layer-1 logits ------
// 32 edges/block, 224 threads (7 warps). cg = tid%28 (col group of 4),
// eg = tid/28 (edge group of 4). Combined 112 output cols:
//   cg 0..15  -> We1 cols 4cg      (64)
//   cg 16..23 -> We2 cols 4(cg-16) (32)
//   cg 24..27 -> We3 cols 4(cg-24) (16)
// K consumed 4 at a time with packed f32x2 FFMA (d-pairs in lo/hi).
__global__ void __launch_bounds__(224) k_edge_proj(
        const float* __restrict__ eattr,
        const int* __restrict__ src, const int* __restrict__ dst,
        const float* __restrict__ We1, const float* __restrict__ We2,
        const float* __restrict__ We3, const float* __restrict__ att1,
        int e) {
    extern __shared__ float sa[];  // [32][388]
    const int tid = threadIdx.x;
    const int eb = blockIdx.x * 32;
    const int nE = min(32, e - eb);

    // cooperative load of 32 edge rows (contiguous in gmem)
    {
        int total = nE * 385;
        const float* gsrc = eattr + (size_t)eb * 385;
        for (int i = tid; i < total; i += 224) {
            int el = i / 385;
            int dl = i - el * 385;
            sa[el * 388 + dl] = gsrc[i];
        }
    }
    __syncthreads();

    const int cg = tid % 28;
    const int eg = tid / 28;

    const float* Wp; int ld, col;
    if (cg < 16)      { Wp = We1; ld = 64; col = cg * 4; }
    else if (cg < 24) { Wp = We2; ld = 32; col = (cg - 16) * 4; }
    else              { Wp = We3; ld = 16; col = (cg - 24) * 4; }

    unsigned long long acc[4][4];
#pragma unroll
    for (int r = 0; r < 4; r++)
#pragma unroll
        for (int j = 0; j < 4; j++) acc[r][j] = 0ull;

    const float* arow = sa + (eg * 4) * 388;

#pragma unroll 2
    for (int d4 = 0; d4 < 96; d4++) {
        int d = d4 * 4;
        float4 w0 = *reinterpret_cast<const float4*>(Wp + (size_t)d * ld + col);
        float4 w1 = *reinterpret_cast<const float4*>(Wp + (size_t)(d + 1) * ld + col);
        float4 w2 = *reinterpret_cast<const float4*>(Wp + (size_t)(d + 2) * ld + col);
        float4 w3 = *reinterpret_cast<const float4*>(Wp + (size_t)(d + 3) * ld + col);
        unsigned long long wa0 = pack2(w0.x, w1.x), wa1 = pack2(w0.y, w1.y);
        unsigned long long wa2 = pack2(w0.z, w1.z), wa3 = pack2(w0.w, w1.w);
        unsigned long long wb0 = pack2(w2.x, w3.x), wb1 = pack2(w2.y, w3.y);
        unsigned long long wb2 = pack2(w2.z, w3.z), wb3 = pack2(w2.w, w3.w);
#pragma unroll
        for (int r = 0; r < 4; r++) {
            ulonglong2 av = *reinterpret_cast<const ulonglong2*>(arow + r * 388 + d);
            fma2(acc[r][0], av.x, wa0); fma2(acc[r][1], av.x, wa1);
            fma2(acc[r][2], av.x, wa2); fma2(acc[r][3], av.x, wa3);
            fma2(acc[r][0], av.y, wb0); fma2(acc[r][1], av.y, wb1);
            fma2(acc[r][2], av.y, wb2); fma2(acc[r][3], av.y, wb3);
        }
    }
    // remainder d = 384 (fold into lo half)
    {
        unsigned long long wr0 = pack2(Wp[(size_t)384 * ld + col + 0], 0.f);
        unsigned long long wr1 = pack2(Wp[(size_t)384 * ld + col + 1], 0.f);
        unsigned long long wr2 = pack2(Wp[(size_t)384 * ld + col + 2], 0.f);
        unsigned long long wr3 = pack2(Wp[(size_t)384 * ld + col + 3], 0.f);
#pragma unroll
        for (int r = 0; r < 4; r++) {
            unsigned long long av = pack2(arow[r * 388 + 384], 0.f);
            fma2(acc[r][0], av, wr0); fma2(acc[r][1], av, wr1);
            fma2(acc[r][2], av, wr2); fma2(acc[r][3], av, wr3);
        }
    }

    // epilogue
#pragma unroll
    for (int r = 0; r < 4; r++) {
        int ee = eb + eg * 4 + r;
        bool valid = ee < e;
        float2 f0 = unpack2(acc[r][0]);
        float2 f1 = unpack2(acc[r][1]);
        float2 f2 = unpack2(acc[r][2]);
        float2 f3 = unpack2(acc[r][3]);
        float s0 = f0.x + f0.y, s1 = f1.x + f1.y;
        float s2 = f2.x + f2.y, s3 = f3.x + f3.y;

        float p = 0.f;
        int t = 0;
        if (cg < 16) {
            int s = valid ? src[ee] : 0;
            t = valid ? dst[ee] : 0;
            float4 xj = *reinterpret_cast<const float4*>(g_xl + (size_t)s * 64 + col);
            float4 xi = *reinterpret_cast<const float4*>(g_xr + (size_t)t * 64 + col);
            float4 at = *reinterpret_cast<const float4*>(att1 + col);
            p = leakyr(xj.x + xi.x + s0) * at.x
              + leakyr(xj.y + xi.y + s1) * at.y
              + leakyr(xj.z + xi.z + s2) * at.z
              + leakyr(xj.w + xi.w + s3) * at.w;
        }
        p += __shfl_xor_sync(0xFFFFFFFFu, p, 1);
        p += __shfl_xor_sync(0xFFFFFFFFu, p, 2);
        if (valid) {
            if (cg < 16) {
                if ((cg & 3) == 0) {
                    int h = cg >> 2;
                    g_logits[(size_t)ee * 4 + h] = p;
                    atomicMaxF(&g_m1[(size_t)t * 4 + h], p);
                }
            } else {
                int off = (cg < 24) ? (cg - 16) * 4 : 32 + (cg - 24) * 4;
                *reinterpret_cast<float4*>(g_ea23 + (size_t)ee * 48 + off) =
                    make_float4(s0, s1, s2, s3);
            }
        }
    }
}

// ---------------- softmax-exp + weighted aggregation (vector red) -----------
__global__ void k_soft1(const int* __restrict__ src, const int* __restrict__ dst, int e) {
    int t = blockIdx.x * blockDim.x + threadIdx.x;
    int ee = t >> 4;
    if (ee >= e) return;
    int q = t & 15, h = q >> 2, c4 = q * 4;
    int s = src[ee], d = dst[ee];
    float ex = expf(g_logits[(size_t)ee * 4 + h] - g_m1[(size_t)d * 4 + h]);
    if ((q & 3) == 0) atomicAdd(&g_s1[(size_t)d * 4 + h], ex);
    float4 x = *reinterpret_cast<const float4*>(g_xl + (size_t)s * 64 + c4);
    red4(g_num1 + (size_t)d * 64 + c4, ex * x.x, ex * x.y, ex * x.z, ex * x.w);
}

__global__ void k_soft2(const int* __restrict__ src, const int* __restrict__ dst, int e) {
    int t = blockIdx.x * blockDim.x + threadIdx.x;
    int ee = t >> 3;
    if (ee >= e) return;
    int q = t & 7, h = q >> 2, c4 = q * 4;
    int s = src[ee], d = dst[ee];
    float ex = expf(g_logits[(size_t)ee * 2 + h] - g_m2[(size_t)d * 2 + h]);
    if ((q & 3) == 0) atomicAdd(&g_s2[(size_t)d * 2 + h], ex);
    float4 x = *reinterpret_cast<const float4*>(g_xl + (size_t)s * 32 + c4);
    red4(g_num2 + (size_t)d * 32 + c4, ex * x.x, ex * x.y, ex * x.z, ex * x.w);
}

__global__ void k_soft3(const int* __restrict__ src, const int* __restrict__ dst, int e) {
    int t = blockIdx.x * blockDim.x + threadIdx.x;
    int ee = t >> 2;
    if (ee >= e) return;
    int q = t & 3, c4 = q * 4;
    int s = src[ee], d = dst[ee];
    float ex = expf(g_logits[ee] - g_m3[d]);
    if (q == 0) atomicAdd(&g_s3[d], ex);
    float4 x = *reinterpret_cast<const float4*>(g_xl + (size_t)s * 16 + c4);
    red4(g_num3 + (size_t)d * 16 + c4, ex * x.x, ex * x.y, ex * x.z, ex * x.w);
}

// ---------------- finish layer1 + project layer2 -----------------------------
__global__ void k_node_fin1(const float* __restrict__ bias1,
                            const float* __restrict__ Wl2, const float* __restrict__ bl2,
                            const float* __restrict__ Wr2, const float* __restrict__ br2,
                            int n) {
    int node = blockIdx.x;
    if (node >= n) return;
    int c = threadIdx.x;  // 0..63
    __shared__ float sx[64];
    float v = g_num1[(size_t)node * 64 + c] / (g_s1[(size_t)node * 4 + (c >> 4)] + 1e-16f) + bias1[c];
    sx[c] = eluf(v);
    __syncthreads();
    if (c < 32) {
        float a = bl2[c];
#pragma unroll
        for (int k = 0; k < 64; k++) a += sx[k] * Wl2[k * 32 + c];
        g_xl[(size_t)node * 32 + c] = a;
        g_num2[(size_t)node * 32 + c] = 0.f;
    } else {
        int c2 = c - 32;
        float a = br2[c2];
#pragma unroll
        for (int k = 0; k < 64; k++) a += sx[k] * Wr2[k * 32 + c2];
        g_xr[(size_t)node * 32 + c2] = a;
    }
    if (c < 2) { g_m2[(size_t)node * 2 + c] = -INFINITY; g_s2[(size_t)node * 2 + c] = 0.f; }
}

// ---------------- layer-2 logits ---------------------------------------------
__global__ void k_edge_logits2(const int* __restrict__ src, const int* __restrict__ dst,
                               const float* __restrict__ att2, int e) {
    int ee = blockIdx.x * 8 + (threadIdx.x >> 5);
    if (ee >= e) return;  // whole warp exits together
    int c = threadIdx.x & 31;
    int s = src[ee], d = dst[ee];
    float ev = leakyr(g_xl[(size_t)s * 32 + c] + g_xr[(size_t)d * 32 + c] + g_ea23[(size_t)ee * 48 + c]);
    float p = ev * att2[c];
    p += __shfl_xor_sync(0xFFFFFFFFu, p, 8);
    p += __shfl_xor_sync(0xFFFFFFFFu, p, 4);
    p += __shfl_xor_sync(0xFFFFFFFFu, p, 2);
    p += __shfl_xor_sync(0xFFFFFFFFu, p, 1);
    if ((c & 15) == 0) {
        int h = c >> 4;
        g_logits[(size_t)ee * 2 + h] = p;
        atomicMaxF(&g_m2[(size_t)d * 2 + h], p);
    }
}

// ---------------- finish layer2 + project layer3 ------------------------------
__global__ void k_node_fin2(const float* __restrict__ bias2,
                            const float* __restrict__ Wl3, const float* __restrict__ bl3,
                            const float* __restrict__ Wr3, const float* __restrict__ br3,
                            int n) {
    int node = blockIdx.x;
    if (node >= n) return;
    int c = threadIdx.x;  // 0..31
    __shared__ float sx[32];
    float v = g_num2[(size_t)node * 32 + c] / (g_s2[(size_t)node * 2 + (c >> 4)] + 1e-16f) + bias2[c];
    sx[c] = eluf(v);
    __syncthreads();
    if (c < 16) {
        float a = bl3[c];
#pragma unroll
        for (int k = 0; k < 32; k++) a += sx[k] * Wl3[k * 16 + c];
        g_xl[(size_t)node * 16 + c] = a;
        g_num3[(size_t)node * 16 + c] = 0.f;
    } else {
        int c2 = c - 16;
        float a = br3[c2];
#pragma unroll
        for (int k = 0; k < 32; k++) a += sx[k] * Wr3[k * 16 + c2];
        g_xr[(size_t)node * 16 + c2] = a;
    }
    if (c == 0) { g_m3[node] = -INFINITY; g_s3[node] = 0.f; }
}

// ---------------- layer-3 logits ----------------------------------------------
__global__ void k_edge_logits3(const int* __restrict__ src, const int* __restrict__ dst,
                               const float* __restrict__ att3, int e) {
    int ee = blockIdx.x * 8 + (threadIdx.x >> 4);
    int c = threadIdx.x & 15;
    bool ok = ee < e;
    int s = ok ? src[ee] : 0, d = ok ? dst[ee] : 0;
    float ev = ok ? leakyr(g_xl[(size_t)s * 16 + c] + g_xr[(size_t)d * 16 + c] + g_ea23[(size_t)ee * 48 + 32 + c]) : 0.f;
    float p = ev * att3[c];
    p += __shfl_xor_sync(0xFFFFFFFFu, p, 8);
    p += __shfl_xor_sync(0xFFFFFFFFu, p, 4);
    p += __shfl_xor_sync(0xFFFFFFFFu, p, 2);
    p += __shfl_xor_sync(0xFFFFFFFFu, p, 1);
    if (ok && c == 0) {
        g_logits[ee] = p;
        atomicMaxF(&g_m3[d], p);
    }
}

// ---------------- finish layer3 ------------------------------------------------
__global__ void k_node_fin3(const float* __restrict__ bias3, int n) {
    int i = blockIdx.x * blockDim.x + threadIdx.x;
    if (i >= n * 16) return;
    g_x3[i] = g_num3[i] / (g_s3[i >> 4] + 1e-16f) + bias3[i & 15];
}

// ---------------- edge MLP: 8 edges per 128-thread block ----------------------
__global__ void k_mlp(const int* __restrict__ src, const int* __restrict__ dst,
                      const float* __restrict__ W1, const float* __restrict__ b1,
                      const float* __restrict__ W2, const float* __restrict__ b2,
                      const float* __restrict__ W3, const float* __restrict__ b3,
                      float* __restrict__ out, int e) {
    __shared__ float h0[8][32], h1[8][64], h2[8][32];
    int tid = threadIdx.x;
    int eb = blockIdx.x * 8;

    for (int i = tid; i < 256; i += 128) {
        int le = i >> 5, j = i & 31;
        int ee = eb + le;
        if (ee < e) {
            int nn = (j < 16) ? src[ee] : dst[ee];
            h0[le][j] = g_x3[(size_t)nn * 16 + (j & 15)];
        }
    }
    __syncthreads();

    // stage 1: h1 = relu(h0 @ W1 + b1). j = col (64), g in {0,1} -> 4 edges each
    {
        int j = tid & 63, g = tid >> 6;
        float a0 = b1[j], a1 = a0, a2 = a0, a3 = a0;
        const float* r0 = h0[g * 4 + 0];
        const float* r1 = h0[g * 4 + 1];
        const float* r2 = h0[g * 4 + 2];
        const float* r3 = h0[g * 4 + 3];
#pragma unroll
        for (int k = 0; k < 32; k++) {
            float w = W1[k * 64 + j];
            a0 += r0[k] * w; a1 += r1[k] * w; a2 += r2[k] * w; a3 += r3[k] * w;
        }
        h1[g * 4 + 0][j] = fmaxf(a0, 0.f);
        h1[g * 4 + 1][j] = fmaxf(a1, 0.f);
        h1[g * 4 + 2][j] = fmaxf(a2, 0.f);
        h1[g * 4 + 3][j] = fmaxf(a3, 0.f);
    }
    __syncthreads();

    // stage 2: h2 = relu(h1 @ W2 + b2). j = col (32), g in 0..3 -> 2 edges each
    {
        int j = tid & 31, g = tid >> 5;
        float a0 = b2[j], a1 = a0;
        const float* r0 = h1[g * 2 + 0];
        const float* r1 = h1[g * 2 + 1];
#pragma unroll
        for (int k = 0; k < 64; k++) {
            float w = W2[k * 32 + j];
            a0 += r0[k] * w; a1 += r1[k] * w;
        }
        h2[g * 2 + 0][j] = fmaxf(a0, 0.f);
        h2[g * 2 + 1][j] = fmaxf(a1, 0.f);
    }
    __syncthreads();

    // stage 3: out = h2 @ W3 + b3. 16 threads per edge
    {
        int e8 = tid >> 4, c = tid & 15;
        float p = h2[e8][c] * W3[c] + h2[e8][c + 16] * W3[c + 16];
        p += __shfl_xor_sync(0xFFFFFFFFu, p, 8);
        p += __shfl_xor_sync(0xFFFFFFFFu, p, 4);
        p += __shfl_xor_sync(0xFFFFFFFFu, p, 2);
        p += __shfl_xor_sync(0xFFFFFFFFu, p, 1);
        int ee = eb + e8;
        if (c == 0 && ee < e) out[ee] = p + b3[0];
    }
}

// ---------------- launch --------------------------------------------------------
extern "C" void kernel_launch(void* const* d_in, const int* in_sizes, int n_in,
                              void* d_out, int out_size) {
    const int*   node_ids = (const int*)  d_in[0];
    const int*   eidx     = (const int*)  d_in[1];
    const float* eattr    = (const float*)d_in[2];
    const float* emb      = (const float*)d_in[3];
    const float* l1_Wl   = (const float*)d_in[4];
    const float* l1_bl   = (const float*)d_in[5];
    const float* l1_Wr   = (const float*)d_in[6];
    const float* l1_br   = (const float*)d_in[7];
    const float* l1_We   = (const float*)d_in[8];
    const float* l1_att  = (const float*)d_in[9];
    const float* l1_bias = (const float*)d_in[10];
    const float* l2_Wl   = (const float*)d_in[11];
    const float* l2_bl   = (const float*)d_in[12];
    const float* l2_Wr   = (const float*)d_in[13];
    const float* l2_br   = (const float*)d_in[14];
    const float* l2_We   = (const float*)d_in[15];
    const float* l2_att  = (const float*)d_in[16];
    const float* l2_bias = (const float*)d_in[17];
    const float* l3_Wl   = (const float*)d_in[18];
    const float* l3_bl   = (const float*)d_in[19];
    const float* l3_Wr   = (const float*)d_in[20];
    const float* l3_br   = (const float*)d_in[21];
    const float* l3_We   = (const float*)d_in[22];
    const float* l3_att  = (const float*)d_in[23];
    const float* l3_bias = (const float*)d_in[24];
    const float* mlp_W1  = (const float*)d_in[25];
    const float* mlp_b1  = (const float*)d_in[26];
    const float* mlp_W2  = (const float*)d_in[27];
    const float* mlp_b2  = (const float*)d_in[28];
    const float* mlp_W3  = (const float*)d_in[29];
    const float* mlp_b3  = (const float*)d_in[30];

    int n = in_sizes[0];
    int e = in_sizes[1] / 2;
    const int* src = eidx;
    const int* dst = eidx + e;
    float* out = (float*)d_out;

    const int SMEM_EP = 32 * 388 * 4;  // 49664 B
    static bool attr_set = false;
    if (!attr_set) {
        cudaFuncSetAttribute(k_edge_proj, cudaFuncAttributeMaxDynamicSharedMemorySize, SMEM_EP);
        attr_set = true;
    }

    // ---- layer 1 ----
    k_node1<<<n, 64>>>(node_ids, emb, l1_Wl, l1_bl, l1_Wr, l1_br, n);
    k_edge_proj<<<(e + 31) / 32, 224, SMEM_EP>>>(eattr, src, dst, l1_We, l2_We, l3_We, l1_att, e);
    k_soft1<<<(e * 16 + 255) / 256, 256>>>(src, dst, e);
    k_node_fin1<<<n, 64>>>(l1_bias, l2_Wl, l2_bl, l2_Wr, l2_br, n);

    // ---- layer 2 ----
    k_edge_logits2<<<(e + 7) / 8, 256>>>(src, dst, l2_att, e);
    k_soft2<<<(e * 8 + 255) / 256, 256>>>(src, dst, e);
    k_node_fin2<<<n, 32>>>(l2_bias, l3_Wl, l3_bl, l3_Wr, l3_br, n);

    // ---- layer 3 ----
    k_edge_logits3<<<(e + 7) / 8, 128>>>(src, dst, l3_att, e);
    k_soft3<<<(e * 4 + 255) / 256, 256>>>(src, dst, e);
    k_node_fin3<<<(n * 16 + 255) / 256, 256>>>(l3_bias, n);

    // ---- edge MLP ----
    k_mlp<<<(e + 7) / 8, 128>>>(src, dst, mlp_W1, mlp_b1, mlp_W2, mlp_b2,
                                mlp_W3, mlp_b3, out, e);
}

// round 3
// speedup vs baseline: 2.2401x; 1.1509x over previous
#include <cuda_runtime.h>
#include <math.h>

#define N_CAP 50048
#define E_CAP 500224
#define KPAD 416          // 385 padded to 13*32
#define NCOL 112          // 64 + 32 + 16 combined output cols

// ---------------- scratch ----------------------------------------------------
__device__ float g_xl[N_CAP * 64];
__device__ float g_xr[N_CAP * 64];
__device__ float g_m1[N_CAP * 4];
__device__ float g_s1[N_CAP * 4];
__device__ float g_num1[N_CAP * 64];
__device__ float g_m2[N_CAP * 2];
__device__ float g_s2[N_CAP * 2];
__device__ float g_num2[N_CAP * 32];
__device__ float g_m3[N_CAP];
__device__ float g_s3[N_CAP];
__device__ float g_num3[N_CAP * 16];
__device__ float g_logits[E_CAP * 4];
__device__ float g_ea23[E_CAP * 48];
__device__ float g_x3[N_CAP * 16];
__device__ float g_Wh[KPAD * NCOL];   // tf32-high split of combined weights
__device__ float g_Wlo[KPAD * NCOL];  // tf32-low  split

// ---------------- helpers ----------------------------------------------------
__device__ __forceinline__ float leakyr(float v) { return v > 0.f ? v : 0.2f * v; }
__device__ __forceinline__ float eluf(float v)   { return v > 0.f ? v : (expf(v) - 1.f); }

__device__ __forceinline__ void atomicMaxF(float* a, float v) {
    if (v >= 0.f) atomicMax(reinterpret_cast<int*>(a), __float_as_int(v));
    else          atomicMin(reinterpret_cast<unsigned int*>(a), __float_as_uint(v));
}
__device__ __forceinline__ void red4(float* p, float a, float b, float c, float d) {
    asm volatile("red.global.add.v4.f32 [%0], {%1, %2, %3, %4};"
                 :: "l"(p), "f"(a), "f"(b), "f"(c), "f"(d) : "memory");
}
__device__ __forceinline__ unsigned tf32r(float x) {
    unsigned r;
    asm("cvt.rna.tf32.f32 %0, %1;" : "=r"(r) : "f"(x));
    return r;
}
__device__ __forceinline__ void mma_tf32(float* d, unsigned a0, unsigned a1,
                                         unsigned a2, unsigned a3,
                                         unsigned b0, unsigned b1) {
    asm volatile(
        "mma.sync.aligned.m16n8k8.row.col.f32.tf32.tf32.f32 "
        "{%0,%1,%2,%3}, {%4,%5,%6,%7}, {%8,%9}, {%0,%1,%2,%3};"
        : "+f"(d[0]), "+f"(d[1]), "+f"(d[2]), "+f"(d[3])
        : "r"(a0), "r"(a1), "r"(a2), "r"(a3), "r"(b0), "r"(b1));
}

// ---------------- weight prep: combined, padded, tf32 hi/lo split -------------
__global__ void k_prep_w(const float* __restrict__ We1, const float* __restrict__ We2,
                         const float* __restrict__ We3) {
    int idx = blockIdx.x * blockDim.x + threadIdx.x;
    if (idx >= KPAD * NCOL) return;
    int k = idx / NCOL, j = idx - k * NCOL;
    float w = 0.f;
    if (k < 385) {
        if (j < 64)      w = We1[k * 64 + j];
        else if (j < 96) w = We2[k * 32 + (j - 64)];
        else             w = We3[k * 16 + (j - 96)];
    }
    unsigned hb = tf32r(w);
    float hf = __uint_as_float(hb);
    g_Wh[idx]  = hf;
    g_Wlo[idx] = __uint_as_float(tf32r(w - hf));
}

// ---------------- layer 1 node projection + init ----------------------------
__global__ void k_node1(const int* __restrict__ node_ids,
                        const float* __restrict__ emb,
                        const float* __restrict__ Wl, const float* __restrict__ bl,
                        const float* __restrict__ Wr, const float* __restrict__ br,
                        int n) {
    int node = blockIdx.x;
    if (node >= n) return;
    int c = threadIdx.x;  // 0..63
    __shared__ float sx[32];
    if (c < 32) sx[c] = emb[node_ids[node] * 32 + c];
    __syncthreads();
    float al = bl[c], ar = br[c];
#pragma unroll
    for (int k = 0; k < 32; k++) {
        float xv = sx[k];
        al += xv * Wl[k * 64 + c];
        ar += xv * Wr[k * 64 + c];
    }
    g_xl[node * 64 + c] = al;
    g_xr[node * 64 + c] = ar;
    g_num1[node * 64 + c] = 0.f;
    if (c < 4) { g_m1[node * 4 + c] = -INFINITY; g_s1[node * 4 + c] = 0.f; }
}

// ---------------- tensor-core edge projection (3x-tf32) + layer-1 logits ------
// 128 edges/block, 4 warps; warp w -> rows [w*32, w*32+32) as 2 m16 tiles.
// N = 112 cols -> 14 n8 tiles. K chunked at 32 (13 chunks over KPAD=416).
#define SA_S 36
#define SB_S 120
__global__ void __launch_bounds__(128, 2) k_edge_mma(
        const float* __restrict__ eattr,
        const int* __restrict__ src, const int* __restrict__ dst,
        const float* __restrict__ att1, int e) {
    extern __shared__ float sm[];
    float* sA  = sm;                        // [128][36]
    float* sBh = sm + 128 * SA_S;           // [32][120]
    float* sBl = sBh + 32 * SB_S;           // [32][120]

    const int tid  = threadIdx.x;
    const int w    = tid >> 5;
    const int lane = tid & 31;
    const int g    = lane >> 2;   // 0..7
    const int c    = lane & 3;    // 0..3
    const int eb   = blockIdx.x * 128;
    const int nE   = min(128, e - eb);

    float D[2][14][4];
#pragma unroll
    for (int tt = 0; tt < 2; tt++)
#pragma unroll
        for (int nt = 0; nt < 14; nt++)
#pragma unroll
            for (int q = 0; q < 4; q++) D[tt][nt][q] = 0.f;

    for (int kc = 0; kc < 13; kc++) {
        __syncthreads();
        // load A chunk [128][32] from eattr (row stride 385, scalar coalesced)
        {
            int k0 = kc * 32;
            for (int i = tid; i < 128 * 32; i += 128) {
                int row = i >> 5, j = i & 31;
                int kk = k0 + j;
                float v = 0.f;
                if (row < nE && kk < 385)
                    v = eattr[(size_t)(eb + row) * 385 + kk];
                sA[row * SA_S + j] = v;
            }
        }
        // load B chunks [32][112] hi/lo (float4)
        {
            const float* bh = g_Wh  + (size_t)kc * 32 * NCOL;
            const float* bl = g_Wlo + (size_t)kc * 32 * NCOL;
            for (int i = tid; i < 896; i += 128) {
                int r = i / 28, cq = (i - r * 28) * 4;
                float4 vh = *reinterpret_cast<const float4*>(bh + r * NCOL + cq);
                float4 vl = *reinterpret_cast<const float4*>(bl + r * NCOL + cq);
                *reinterpret_cast<float4*>(sBh + r * SB_S + cq) = vh;
                *reinterpret_cast<float4*>(sBl + r * SB_S + cq) = vl;
            }
        }
        __syncthreads();

#pragma unroll
        for (int k8 = 0; k8 < 4; k8++) {
            int kb = k8 * 8;
            unsigned ah[2][4], al[2][4];
#pragma unroll
            for (int tt = 0; tt < 2; tt++) {
                int m0 = w * 32 + tt * 16;
                float a0 = sA[(m0 + g)     * SA_S + kb + c];
                float a1 = sA[(m0 + g + 8) * SA_S + kb + c];
                float a2 = sA[(m0 + g)     * SA_S + kb + c + 4];
                float a3 = sA[(m0 + g + 8) * SA_S + kb + c + 4];
                ah[tt][0] = tf32r(a0); al[tt][0] = tf32r(a0 - __uint_as_float(ah[tt][0]));
                ah[tt][1] = tf32r(a1); al[tt][1] = tf32r(a1 - __uint_as_float(ah[tt][1]));
                ah[tt][2] = tf32r(a2); al[tt][2] = tf32r(a2 - __uint_as_float(ah[tt][2]));
                ah[tt][3] = tf32r(a3); al[tt][3] = tf32r(a3 - __uint_as_float(ah[tt][3]));
            }
#pragma unroll
            for (int nt = 0; nt < 14; nt++) {
                int nb = nt * 8 + g;
                unsigned b0h = __float_as_uint(sBh[(kb + c)     * SB_S + nb]);
                unsigned b1h = __float_as_uint(sBh[(kb + c + 4) * SB_S + nb]);
                unsigned b0l = __float_as_uint(sBl[(kb + c)     * SB_S + nb]);
                unsigned b1l = __float_as_uint(sBl[(kb + c + 4) * SB_S + nb]);
#pragma unroll
                for (int tt = 0; tt < 2; tt++) {
                    mma_tf32(D[tt][nt], ah[tt][0], ah[tt][1], ah[tt][2], ah[tt][3], b0h, b1h);
                    mma_tf32(D[tt][nt], al[tt][0], al[tt][1], al[tt][2], al[tt][3], b0h, b1h);
                    mma_tf32(D[tt][nt], ah[tt][0], ah[tt][1], ah[tt][2], ah[tt][3], b0l, b1l);
                }
            }
        }
    }

    // -------- epilogue: fragments -> logits1 + ea23 stores --------
#pragma unroll
    for (int tt = 0; tt < 2; tt++) {
        int m0 = w * 32 + tt * 16;
        int rA = m0 + g, rB = m0 + g + 8;
        int eeA = eb + rA, eeB = eb + rB;
        bool vA = rA < nE, vB = rB < nE;
        int sA_ = vA ? src[eeA] : 0, dA_ = vA ? dst[eeA] : 0;
        int sB_ = vB ? src[eeB] : 0, dB_ = vB ? dst[eeB] : 0;

        // layer-1 logits: cols 0..63 = n-tiles 0..7, head h = nt>>1
#pragma unroll
        for (int h = 0; h < 4; h++) {
            float pA = 0.f, pB = 0.f;
#pragma unroll
            for (int q = 0; q < 2; q++) {
                int nt = 2 * h + q;
                int col = nt * 8 + c * 2;
                float at0 = att1[col], at1 = att1[col + 1];
                float2 xjA = *reinterpret_cast<const float2*>(g_xl + (size_t)sA_ * 64 + col);
                float2 xiA = *reinterpret_cast<const float2*>(g_xr + (size_t)dA_ * 64 + col);
                pA += leakyr(D[tt][nt][0] + xjA.x + xiA.x) * at0
                    + leakyr(D[tt][nt][1] + xjA.y + xiA.y) * at1;
                float2 xjB = *reinterpret_cast<const float2*>(g_xl + (size_t)sB_ * 64 + col);
                float2 xiB = *reinterpret_cast<const float2*>(g_xr + (size_t)dB_ * 64 + col);
                pB += leakyr(D[tt][nt][2] + xjB.x + xiB.x) * at0
                    + leakyr(D[tt][nt][3] + xjB.y + xiB.y) * at1;
            }
            pA += __shfl_xor_sync(0xFFFFFFFFu, pA, 1);
            pA += __shfl_xor_sync(0xFFFFFFFFu, pA, 2);
            pB += __shfl_xor_sync(0xFFFFFFFFu, pB, 1);
            pB += __shfl_xor_sync(0xFFFFFFFFu, pB, 2);
            if (c == 0) {
                if (vA) {
                    g_logits[(size_t)eeA * 4 + h] = pA;
                    atomicMaxF(&g_m1[(size_t)dA_ * 4 + h], pA);
                }
                if (vB) {
                    g_logits[(size_t)eeB * 4 + h] = pB;
                    atomicMaxF(&g_m1[(size_t)dB_ * 4 + h], pB);
                }
            }
        }
        // ea23: n-tiles 8..13 -> g_ea23[ee*48 + off]
#pragma unroll
        for (int nt = 8; nt < 14; nt++) {
            int off = (nt < 12) ? (nt - 8) * 8 + c * 2
                                : 32 + (nt - 12) * 8 + c * 2;
            if (vA) *reinterpret_cast<float2*>(g_ea23 + (size_t)eeA * 48 + off) =
                        make_float2(D[tt][nt][0], D[tt][nt][1]);
            if (vB) *reinterpret_cast<float2*>(g_ea23 + (size_t)eeB * 48 + off) =
                        make_float2(D[tt][nt][2], D[tt][nt][3]);
        }
    }
}

// ---------------- softmax-exp + weighted aggregation (vector red) -----------
__global__ void k_soft1(const int* __restrict__ src, const int* __restrict__ dst, int e) {
    int t = blockIdx.x * blockDim.x + threadIdx.x;
    int ee = t >> 4;
    if (ee >= e) return;
    int q = t & 15, h = q >> 2, c4 = q * 4;
    int s = src[ee], d = dst[ee];
    float ex = expf(g_logits[(size_t)ee * 4 + h] - g_m1[(size_t)d * 4 + h]);
    if ((q & 3) == 0) atomicAdd(&g_s1[(size_t)d * 4 + h], ex);
    float4 x = *reinterpret_cast<const float4*>(g_xl + (size_t)s * 64 + c4);
    red4(g_num1 + (size_t)d * 64 + c4, ex * x.x, ex * x.y, ex * x.z, ex * x.w);
}

__global__ void k_soft2(const int* __restrict__ src, const int* __restrict__ dst, int e) {
    int t = blockIdx.x * blockDim.x + threadIdx.x;
    int ee = t >> 3;
    if (ee >= e) return;
    int q = t & 7, h = q >> 2, c4 = q * 4;
    int s = src[ee], d = dst[ee];
    float ex = expf(g_logits[(size_t)ee * 2 + h] - g_m2[(size_t)d * 2 + h]);
    if ((q & 3) == 0) atomicAdd(&g_s2[(size_t)d * 2 + h], ex);
    float4 x = *reinterpret_cast<const float4*>(g_xl + (size_t)s * 32 + c4);
    red4(g_num2 + (size_t)d * 32 + c4, ex * x.x, ex * x.y, ex * x.z, ex * x.w);
}

__global__ void k_soft3(const int* __restrict__ src, const int* __restrict__ dst, int e) {
    int t = blockIdx.x * blockDim.x + threadIdx.x;
    int ee = t >> 2;
    if (ee >= e) return;
    int q = t & 3, c4 = q * 4;
    int s = src[ee], d = dst[ee];
    float ex = expf(g_logits[ee] - g_m3[d]);
    if (q == 0) atomicAdd(&g_s3[d], ex);
    float4 x = *reinterpret_cast<const float4*>(g_xl + (size_t)s * 16 + c4);
    red4(g_num3 + (size_t)d * 16 + c4, ex * x.x, ex * x.y, ex * x.z, ex * x.w);
}

// ---------------- finish layer1 + project layer2 -----------------------------
__global__ void k_node_fin1(const float* __restrict__ bias1,
                            const float* __restrict__ Wl2, const float* __restrict__ bl2,
                            const float* __restrict__ Wr2, const float* __restrict__ br2,
                            int n) {
    int node = blockIdx.x;
    if (node >= n) return;
    int c = threadIdx.x;  // 0..63
    __shared__ float sx[64];
    float v = g_num1[(size_t)node * 64 + c] / (g_s1[(size_t)node * 4 + (c >> 4)] + 1e-16f) + bias1[c];
    sx[c] = eluf(v);
    __syncthreads();
    if (c < 32) {
        float a = bl2[c];
#pragma unroll
        for (int k = 0; k < 64; k++) a += sx[k] * Wl2[k * 32 + c];
        g_xl[(size_t)node * 32 + c] = a;
        g_num2[(size_t)node * 32 + c] = 0.f;
    } else {
        int c2 = c - 32;
        float a = br2[c2];
#pragma unroll
        for (int k = 0; k < 64; k++) a += sx[k] * Wr2[k * 32 + c2];
        g_xr[(size_t)node * 32 + c2] = a;
    }
    if (c < 2) { g_m2[(size_t)node * 2 + c] = -INFINITY; g_s2[(size_t)node * 2 + c] = 0.f; }
}

// ---------------- layer-2 logits ---------------------------------------------
__global__ void k_edge_logits2(const int* __restrict__ src, const int* __restrict__ dst,
                               const float* __restrict__ att2, int e) {
    int ee = blockIdx.x * 8 + (threadIdx.x >> 5);
    if (ee >= e) return;  // whole warp exits together
    int c = threadIdx.x & 31;
    int s = src[ee], d = dst[ee];
    float ev = leakyr(g_xl[(size_t)s * 32 + c] + g_xr[(size_t)d * 32 + c] + g_ea23[(size_t)ee * 48 + c]);
    float p = ev * att2[c];
    p += __shfl_xor_sync(0xFFFFFFFFu, p, 8);
    p += __shfl_xor_sync(0xFFFFFFFFu, p, 4);
    p += __shfl_xor_sync(0xFFFFFFFFu, p, 2);
    p += __shfl_xor_sync(0xFFFFFFFFu, p, 1);
    if ((c & 15) == 0) {
        int h = c >> 4;
        g_logits[(size_t)ee * 2 + h] = p;
        atomicMaxF(&g_m2[(size_t)d * 2 + h], p);
    }
}

// ---------------- finish layer2 + project layer3 ------------------------------
__global__ void k_node_fin2(const float* __restrict__ bias2,
                            const float* __restrict__ Wl3, const float* __restrict__ bl3,
                            const float* __restrict__ Wr3, const float* __restrict__ br3,
                            int n) {
    int node = blockIdx.x;
    if (node >= n) return;
    int c = threadIdx.x;  // 0..31
    __shared__ float sx[32];
    float v = g_num2[(size_t)node * 32 + c] / (g_s2[(size_t)node * 2 + (c >> 4)] + 1e-16f) + bias2[c];
    sx[c] = eluf(v);
    __syncthreads();
    if (c < 16) {
        float a = bl3[c];
#pragma unroll
        for (int k = 0; k < 32; k++) a += sx[k] * Wl3[k * 16 + c];
        g_xl[(size_t)node * 16 + c] = a;
        g_num3[(size_t)node * 16 + c] = 0.f;
    } else {
        int c2 = c - 16;
        float a = br3[c2];
#pragma unroll
        for (int k = 0; k < 32; k++) a += sx[k] * Wr3[k * 16 + c2];
        g_xr[(size_t)node * 16 + c2] = a;
    }
    if (c == 0) { g_m3[node] = -INFINITY; g_s3[node] = 0.f; }
}

// ---------------- layer-3 logits ----------------------------------------------
__global__ void k_edge_logits3(const int* __restrict__ src, const int* __restrict__ dst,
                               const float* __restrict__ att3, int e) {
    int ee = blockIdx.x * 8 + (threadIdx.x >> 4);
    int c = threadIdx.x & 15;
    bool ok = ee < e;
    int s = ok ? src[ee] : 0, d = ok ? dst[ee] : 0;
    float ev = ok ? leakyr(g_xl[(size_t)s * 16 + c] + g_xr[(size_t)d * 16 + c] + g_ea23[(size_t)ee * 48 + 32 + c]) : 0.f;
    float p = ev * att3[c];
    p += __shfl_xor_sync(0xFFFFFFFFu, p, 8);
    p += __shfl_xor_sync(0xFFFFFFFFu, p, 4);
    p += __shfl_xor_sync(0xFFFFFFFFu, p, 2);
    p += __shfl_xor_sync(0xFFFFFFFFu, p, 1);
    if (ok && c == 0) {
        g_logits[ee] = p;
        atomicMaxF(&g_m3[d], p);
    }
}

// ---------------- finish layer3 ------------------------------------------------
__global__ void k_node_fin3(const float* __restrict__ bias3, int n) {
    int i = blockIdx.x * blockDim.x + threadIdx.x;
    if (i >= n * 16) return;
    g_x3[i] = g_num3[i] / (g_s3[i >> 4] + 1e-16f) + bias3[i & 15];
}

// ---------------- edge MLP: 8 edges per 128-thread block ----------------------
__global__ void k_mlp(const int* __restrict__ src, const int* __restrict__ dst,
                      const float* __restrict__ W1, const float* __restrict__ b1,
                      const float* __restrict__ W2, const float* __restrict__ b2,
                      const float* __restrict__ W3, const float* __restrict__ b3,
                      float* __restrict__ out, int e) {
    __shared__ float h0[8][32], h1[8][64], h2[8][32];
    int tid = threadIdx.x;
    int eb = blockIdx.x * 8;

    for (int i = tid; i < 256; i += 128) {
        int le = i >> 5, j = i & 31;
        int ee = eb + le;
        if (ee < e) {
            int nn = (j < 16) ? src[ee] : dst[ee];
            h0[le][j] = g_x3[(size_t)nn * 16 + (j & 15)];
        }
    }
    __syncthreads();

    {
        int j = tid & 63, g = tid >> 6;
        float a0 = b1[j], a1 = a0, a2 = a0, a3 = a0;
        const float* r0 = h0[g * 4 + 0];
        const float* r1 = h0[g * 4 + 1];
        const float* r2 = h0[g * 4 + 2];
        const float* r3 = h0[g * 4 + 3];
#pragma unroll
        for (int k = 0; k < 32; k++) {
            float w = W1[k * 64 + j];
            a0 += r0[k] * w; a1 += r1[k] * w; a2 += r2[k] * w; a3 += r3[k] * w;
        }
        h1[g * 4 + 0][j] = fmaxf(a0, 0.f);
        h1[g * 4 + 1][j] = fmaxf(a1, 0.f);
        h1[g * 4 + 2][j] = fmaxf(a2, 0.f);
        h1[g * 4 + 3][j] = fmaxf(a3, 0.f);
    }
    __syncthreads();

    {
        int j = tid & 31, g = tid >> 5;
        float a0 = b2[j], a1 = a0;
        const float* r0 = h1[g * 2 + 0];
        const float* r1 = h1[g * 2 + 1];
#pragma unroll
        for (int k = 0; k < 64; k++) {
            float w = W2[k * 32 + j];
            a0 += r0[k] * w; a1 += r1[k] * w;
        }
        h2[g * 2 + 0][j] = fmaxf(a0, 0.f);
        h2[g * 2 + 1][j] = fmaxf(a1, 0.f);
    }
    __syncthreads();

    {
        int e8 = tid >> 4, c = tid & 15;
        float p = h2[e8][c] * W3[c] + h2[e8][c + 16] * W3[c + 16];
        p += __shfl_xor_sync(0xFFFFFFFFu, p, 8);
        p += __shfl_xor_sync(0xFFFFFFFFu, p, 4);
        p += __shfl_xor_sync(0xFFFFFFFFu, p, 2);
        p += __shfl_xor_sync(0xFFFFFFFFu, p, 1);
        int ee = eb + e8;
        if (c == 0 && ee < e) out[ee] = p + b3[0];
    }
}

// ---------------- launch --------------------------------------------------------
extern "C" void kernel_launch(void* const* d_in, const int* in_sizes, int n_in,
                              void* d_out, int out_size) {
    const int*   node_ids = (const int*)  d_in[0];
    const int*   eidx     = (const int*)  d_in[1];
    const float* eattr    = (const float*)d_in[2];
    const float* emb      = (const float*)d_in[3];
    const float* l1_Wl   = (const float*)d_in[4];
    const float* l1_bl   = (const float*)d_in[5];
    const float* l1_Wr   = (const float*)d_in[6];
    const float* l1_br   = (const float*)d_in[7];
    const float* l1_We   = (const float*)d_in[8];
    const float* l1_att  = (const float*)d_in[9];
    const float* l1_bias = (const float*)d_in[10];
    const float* l2_Wl   = (const float*)d_in[11];
    const float* l2_bl   = (const float*)d_in[12];
    const float* l2_Wr   = (const float*)d_in[13];
    const float* l2_br   = (const float*)d_in[14];
    const float* l2_We   = (const float*)d_in[15];
    const float* l2_att  = (const float*)d_in[16];
    const float* l2_bias = (const float*)d_in[17];
    const float* l3_Wl   = (const float*)d_in[18];
    const float* l3_bl   = (const float*)d_in[19];
    const float* l3_Wr   = (const float*)d_in[20];
    const float* l3_br   = (const float*)d_in[21];
    const float* l3_We   = (const float*)d_in[22];
    const float* l3_att  = (const float*)d_in[23];
    const float* l3_bias = (const float*)d_in[24];
    const float* mlp_W1  = (const float*)d_in[25];
    const float* mlp_b1  = (const float*)d_in[26];
    const float* mlp_W2  = (const float*)d_in[27];
    const float* mlp_b2  = (const float*)d_in[28];
    const float* mlp_W3  = (const float*)d_in[29];
    const float* mlp_b3  = (const float*)d_in[30];

    int n = in_sizes[0];
    int e = in_sizes[1] / 2;
    const int* src = eidx;
    const int* dst = eidx + e;
    float* out = (float*)d_out;

    const int SMEM_MMA = (128 * SA_S + 2 * 32 * SB_S) * 4;  // 49152 B
    static bool attr_set = false;
    if (!attr_set) {
        cudaFuncSetAttribute(k_edge_mma, cudaFuncAttributeMaxDynamicSharedMemorySize, SMEM_MMA);
        attr_set = true;
    }

    // ---- prep + layer 1 ----
    k_prep_w<<<(KPAD * NCOL + 255) / 256, 256>>>(l1_We, l2_We, l3_We);
    k_node1<<<n, 64>>>(node_ids, emb, l1_Wl, l1_bl, l1_Wr, l1_br, n);
    k_edge_mma<<<(e + 127) / 128, 128, SMEM_MMA>>>(eattr, src, dst, l1_att, e);
    k_soft1<<<(e * 16 + 255) / 256, 256>>>(src, dst, e);
    k_node_fin1<<<n, 64>>>(l1_bias, l2_Wl, l2_bl, l2_Wr, l2_br, n);

    // ---- layer 2 ----
    k_edge_logits2<<<(e + 7) / 8, 256>>>(src, dst, l2_att, e);
    k_soft2<<<(e * 8 + 255) / 256, 256>>>(src, dst, e);
    k_node_fin2<<<n, 32>>>(l2_bias, l3_Wl, l3_bl, l3_Wr, l3_br, n);

    // ---- layer 3 ----
    k_edge_logits3<<<(e + 7) / 8, 128>>>(src, dst, l3_att, e);
    k_soft3<<<(e * 4 + 255) / 256, 256>>>(src, dst, e);
    k_node_fin3<<<(n * 16 + 255) / 256, 256>>>(l3_bias, n);

    // ---- edge MLP ----
    k_mlp<<<(e + 7) / 8, 128>>>(src, dst, mlp_W1, mlp_b1, mlp_W2, mlp_b2,
                                mlp_W3, mlp_b3, out, e);
}

// round 5
// speedup vs baseline: 4.7286x; 2.1109x over previous
#include <cuda_runtime.h>
#include <cuda_bf16.h>
#include <math.h>
#include <stdint.h>

#define N_CAP 50048
#define E_CAP 500224
#define KPAD 416          // 385 padded to 13*32
#define NCOL 112          // 64 + 32 + 16 combined output cols

// ---------------- scratch ----------------------------------------------------
__device__ float g_xl[N_CAP * 64];
__device__ float g_xr[N_CAP * 64];
__device__ float g_m1[N_CAP * 4];
__device__ float g_s1[N_CAP * 4];
__device__ float g_num1[N_CAP * 64];
__device__ float g_m2[N_CAP * 2];
__device__ float g_s2[N_CAP * 2];
__device__ float g_num2[N_CAP * 32];
__device__ float g_m3[N_CAP];
__device__ float g_s3[N_CAP];
__device__ float g_num3[N_CAP * 16];
__device__ float g_logits[E_CAP * 4];
__device__ float g_ea23[E_CAP * 48];
__device__ float g_x3[N_CAP * 16];
__device__ __nv_bfloat16 g_Bh[NCOL * KPAD];  // [112][416] row-major (n-major)
__device__ __nv_bfloat16 g_Bl[NCOL * KPAD];

// ---------------- helpers ----------------------------------------------------
__device__ __forceinline__ float leakyr(float v) { return v > 0.f ? v : 0.2f * v; }
__device__ __forceinline__ float eluf(float v)   { return v > 0.f ? v : (expf(v) - 1.f); }

__device__ __forceinline__ void atomicMaxF(float* a, float v) {
    if (v >= 0.f) atomicMax(reinterpret_cast<int*>(a), __float_as_int(v));
    else          atomicMin(reinterpret_cast<unsigned int*>(a), __float_as_uint(v));
}
__device__ __forceinline__ void red4(float* p, float a, float b, float c, float d) {
    asm volatile("red.global.add.v4.f32 [%0], {%1, %2, %3, %4};"
                 :: "l"(p), "f"(a), "f"(b), "f"(c), "f"(d) : "memory");
}
__device__ __forceinline__ uint32_t smem_u32(const void* p) {
    uint32_t a;
    asm("{ .reg .u64 t; cvta.to.shared.u64 t, %1; cvt.u32.u64 %0, t; }" : "=r"(a) : "l"(p));
    return a;
}
__device__ __forceinline__ void mma_bf16(float* d, uint32_t a0, uint32_t a1,
                                         uint32_t a2, uint32_t a3,
                                         uint32_t b0, uint32_t b1) {
    asm volatile(
        "mma.sync.aligned.m16n8k16.row.col.f32.bf16.bf16.f32 "
        "{%0,%1,%2,%3}, {%4,%5,%6,%7}, {%8,%9}, {%0,%1,%2,%3};"
        : "+f"(d[0]), "+f"(d[1]), "+f"(d[2]), "+f"(d[3])
        : "r"(a0), "r"(a1), "r"(a2), "r"(a3), "r"(b0), "r"(b1));
}
__device__ __forceinline__ void cp16(uint32_t dst_smem, const void* src) {
    asm volatile("cp.async.cg.shared.global [%0], [%1], 16;"
                 :: "r"(dst_smem), "l"(src) : "memory");
}
#define CP_COMMIT()  asm volatile("cp.async.commit_group;" ::: "memory")
#define CP_WAIT(n)   asm volatile("cp.async.wait_group %0;" :: "n"(n) : "memory")

// ---------------- weight prep: combined, padded, bf16 hi/lo, [n][k] ----------
__global__ void k_prep_w(const float* __restrict__ We1, const float* __restrict__ We2,
                         const float* __restrict__ We3) {
    int idx = blockIdx.x * blockDim.x + threadIdx.x;
    if (idx >= NCOL * KPAD) return;
    int j = idx / KPAD, k = idx - j * KPAD;
    float w = 0.f;
    if (k < 385) {
        if (j < 64)      w = We1[k * 64 + j];
        else if (j < 96) w = We2[k * 32 + (j - 64)];
        else             w = We3[k * 16 + (j - 96)];
    }
    __nv_bfloat16 h = __float2bfloat16(w);
    __nv_bfloat16 l = __float2bfloat16(w - __bfloat162float(h));
    g_Bh[idx] = h;
    g_Bl[idx] = l;
}

// ---------------- layer 1 node projection -----------------------------------
__global__ void k_node1(const int* __restrict__ node_ids,
                        const float* __restrict__ emb,
                        const float* __restrict__ Wl, const float* __restrict__ bl,
                        const float* __restrict__ Wr, const float* __restrict__ br,
                        int n) {
    int node = blockIdx.x;
    if (node >= n) return;
    int c = threadIdx.x;  // 0..63
    __shared__ float sx[32];
    if (c < 32) sx[c] = emb[node_ids[node] * 32 + c];
    __syncthreads();
    float al = bl[c], ar = br[c];
#pragma unroll
    for (int k = 0; k < 32; k++) {
        float xv = sx[k];
        al += xv * Wl[k * 64 + c];
        ar += xv * Wr[k * 64 + c];
    }
    g_xl[node * 64 + c] = al;
    g_xr[node * 64 + c] = ar;
}

// ---------------- init layer-1 accumulators (3rd launch -> edge is 4th) ------
__global__ void k_init1(int n) {
    int i = blockIdx.x * blockDim.x + threadIdx.x;
    if (i < n * 64) g_num1[i] = 0.f;
    if (i < n * 4) { g_m1[i] = -INFINITY; g_s1[i] = 0.f; }
}

// ---------------- bf16 mma.sync edge projection + layer-1 logits -------------
// 128 edges/CTA; N=112 (14 n8 tiles); K chunks of 32 (13 chunks).
// A: fp32 LDG register pipeline -> bf16 hi/lo smem (single stage).
// B: pre-split bf16 hi/lo via cp.async (2-stage double buffer).
#define SA_STRIDE 36     // bf16 per row (32 + 4 pad) -> 72B
#define SB_STRIDE 40     // bf16 per row (32 + 8 pad) -> 80B, 16B-aligned rows
#define SM_AH 0
#define SM_AL (128 * SA_STRIDE * 2)                   // 9216
#define SM_BH (SM_AL + 128 * SA_STRIDE * 2)           // 18432, [2][112][40]
#define SM_BL (SM_BH + 2 * 112 * SB_STRIDE * 2)       // 36352
#define SM_EP_TOTAL (SM_BL + 2 * 112 * SB_STRIDE * 2) // 54272

__global__ void __launch_bounds__(128, 2) k_edge_mma(
        const float* __restrict__ eattr,
        const int* __restrict__ src, const int* __restrict__ dst,
        const float* __restrict__ att1, int e) {
    extern __shared__ char smem[];
    __nv_bfloat16* sAh = reinterpret_cast<__nv_bfloat16*>(smem + SM_AH);
    __nv_bfloat16* sAl = reinterpret_cast<__nv_bfloat16*>(smem + SM_AL);
    const uint32_t sBh_u = smem_u32(smem + SM_BH);
    const uint32_t sBl_u = smem_u32(smem + SM_BL);

    const int tid  = threadIdx.x;
    const int w    = tid >> 5;
    const int lane = tid & 31;
    const int g    = lane >> 2;
    const int c    = lane & 3;
    const int eb   = blockIdx.x * 128;
    const int nE   = min(128, e - eb);

    float D[2][14][4];
#pragma unroll
    for (int tt = 0; tt < 2; tt++)
#pragma unroll
        for (int nt = 0; nt < 14; nt++)
#pragma unroll
            for (int q = 0; q < 4; q++) D[tt][nt][q] = 0.f;

    float aR[32];  // 16 fp32 pairs for next chunk

    // --- A LDG for chunk kc into aR: pair p = it*128+tid -> row p/16, colpair p%16
#define LOAD_A(kc_)                                                          \
    {                                                                        \
        int k0 = (kc_) * 32;                                                 \
        _Pragma("unroll")                                                    \
        for (int it = 0; it < 16; it++) {                                    \
            int p = it * 128 + tid;                                          \
            int row = p >> 4, cp = p & 15;                                   \
            int col = k0 + cp * 2;                                           \
            float v0 = 0.f, v1 = 0.f;                                        \
            if (row < nE) {                                                  \
                const float* rp = eattr + (size_t)(eb + row) * 385;          \
                if (col < 385)     v0 = rp[col];                             \
                if (col + 1 < 385) v1 = rp[col + 1];                         \
            }                                                                \
            aR[2 * it] = v0; aR[2 * it + 1] = v1;                            \
        }                                                                    \
    }

#define STORE_A()                                                            \
    {                                                                        \
        _Pragma("unroll")                                                    \
        for (int it = 0; it < 16; it++) {                                    \
            int p = it * 128 + tid;                                          \
            int row = p >> 4, cp = p & 15;                                   \
            float v0 = aR[2 * it], v1 = aR[2 * it + 1];                      \
            __nv_bfloat16 h0 = __float2bfloat16(v0);                         \
            __nv_bfloat16 h1 = __float2bfloat16(v1);                         \
            __nv_bfloat16 l0 = __float2bfloat16(v0 - __bfloat162float(h0));  \
            __nv_bfloat16 l1 = __float2bfloat16(v1 - __bfloat162float(h1));  \
            int o = row * SA_STRIDE + cp * 2;                                \
            *reinterpret_cast<__nv_bfloat162*>(sAh + o) = __nv_bfloat162(h0, h1); \
            *reinterpret_cast<__nv_bfloat162*>(sAl + o) = __nv_bfloat162(l0, l1); \
        }                                                                    \
    }

    // --- cp.async B chunk (hi+lo), 112 rows x 64B each per split
#define CA_B(kc_, buf_)                                                      \
    {                                                                        \
        const char* bh = reinterpret_cast<const char*>(g_Bh);                \
        const char* bl = reinterpret_cast<const char*>(g_Bl);                \
        int koff = (kc_) * 64;                                               \
        uint32_t dsth = sBh_u + (buf_) * 112 * SB_STRIDE * 2;                \
        uint32_t dstl = sBl_u + (buf_) * 112 * SB_STRIDE * 2;                \
        for (int i = tid; i < 448; i += 128) {                               \
            int row = i >> 2, q = i & 3;                                     \
            cp16(dsth + row * (SB_STRIDE * 2) + q * 16,                      \
                 bh + (size_t)row * (KPAD * 2) + koff + q * 16);             \
            cp16(dstl + row * (SB_STRIDE * 2) + q * 16,                      \
                 bl + (size_t)row * (KPAD * 2) + koff + q * 16);             \
        }                                                                    \
    }

    // prologue
    LOAD_A(0);
    CA_B(0, 0);
    CP_COMMIT();

    for (int kc = 0; kc < 13; kc++) {
        __syncthreads();           // previous MMA done -> safe to overwrite sA / sB[(kc+1)&1]
        STORE_A();
        if (kc < 12) {
            LOAD_A(kc + 1);
            CA_B(kc + 1, (kc + 1) & 1);
            CP_COMMIT();
            CP_WAIT(1);
        } else {
            CP_WAIT(0);
        }
        __syncthreads();           // sA stored by all, B chunk kc visible

        const __nv_bfloat16* bhp = reinterpret_cast<const __nv_bfloat16*>(smem + SM_BH)
                                   + (kc & 1) * 112 * SB_STRIDE;
        const __nv_bfloat16* blp = reinterpret_cast<const __nv_bfloat16*>(smem + SM_BL)
                                   + (kc & 1) * 112 * SB_STRIDE;
#pragma unroll
        for (int k16 = 0; k16 < 2; k16++) {
            int kb = k16 * 16;
            uint32_t ah[2][4], al_[2][4];
#pragma unroll
            for (int tt = 0; tt < 2; tt++) {
                int m0 = w * 32 + tt * 16;
                int rA = (m0 + g) * SA_STRIDE, rB = (m0 + g + 8) * SA_STRIDE;
                int c0 = kb + 2 * c, c1 = kb + 2 * c + 8;
                ah[tt][0] = *reinterpret_cast<const uint32_t*>(sAh + rA + c0);
                ah[tt][1] = *reinterpret_cast<const uint32_t*>(sAh + rB + c0);
                ah[tt][2] = *reinterpret_cast<const uint32_t*>(sAh + rA + c1);
                ah[tt][3] = *reinterpret_cast<const uint32_t*>(sAh + rB + c1);
                al_[tt][0] = *reinterpret_cast<const uint32_t*>(sAl + rA + c0);
                al_[tt][1] = *reinterpret_cast<const uint32_t*>(sAl + rB + c0);
                al_[tt][2] = *reinterpret_cast<const uint32_t*>(sAl + rA + c1);
                al_[tt][3] = *reinterpret_cast<const uint32_t*>(sAl + rB + c1);
            }
#pragma unroll
            for (int nt = 0; nt < 14; nt++) {
                int n = nt * 8 + g;
                int c0 = kb + 2 * c, c1 = kb + 2 * c + 8;
                uint32_t bh0 = *reinterpret_cast<const uint32_t*>(bhp + n * SB_STRIDE + c0);
                uint32_t bh1 = *reinterpret_cast<const uint32_t*>(bhp + n * SB_STRIDE + c1);
                uint32_t bl0 = *reinterpret_cast<const uint32_t*>(blp + n * SB_STRIDE + c0);
                uint32_t bl1 = *reinterpret_cast<const uint32_t*>(blp + n * SB_STRIDE + c1);
#pragma unroll
                for (int tt = 0; tt < 2; tt++) {
                    mma_bf16(D[tt][nt], ah[tt][0], ah[tt][1], ah[tt][2], ah[tt][3], bh0, bh1);
                    mma_bf16(D[tt][nt], al_[tt][0], al_[tt][1], al_[tt][2], al_[tt][3], bh0, bh1);
                    mma_bf16(D[tt][nt], ah[tt][0], ah[tt][1], ah[tt][2], ah[tt][3], bl0, bl1);
                }
            }
        }
    }

    // -------- epilogue: fragments -> logits1 + ea23 stores --------
#pragma unroll
    for (int tt = 0; tt < 2; tt++) {
        int m0 = w * 32 + tt * 16;
        int rA = m0 + g, rB = m0 + g + 8;
        int eeA = eb + rA, eeB = eb + rB;
        bool vA = rA < nE, vB = rB < nE;
        int sA_ = vA ? src[eeA] : 0, dA_ = vA ? dst[eeA] : 0;
        int sB_ = vB ? src[eeB] : 0, dB_ = vB ? dst[eeB] : 0;

#pragma unroll
        for (int h = 0; h < 4; h++) {
            float pA = 0.f, pB = 0.f;
#pragma unroll
            for (int q = 0; q < 2; q++) {
                int nt = 2 * h + q;
                int col = nt * 8 + c * 2;
                float at0 = att1[col], at1 = att1[col + 1];
                float2 xjA = *reinterpret_cast<const float2*>(g_xl + (size_t)sA_ * 64 + col);
                float2 xiA = *reinterpret_cast<const float2*>(g_xr + (size_t)dA_ * 64 + col);
                pA += leakyr(D[tt][nt][0] + xjA.x + xiA.x) * at0
                    + leakyr(D[tt][nt][1] + xjA.y + xiA.y) * at1;
                float2 xjB = *reinterpret_cast<const float2*>(g_xl + (size_t)sB_ * 64 + col);
                float2 xiB = *reinterpret_cast<const float2*>(g_xr + (size_t)dB_ * 64 + col);
                pB += leakyr(D[tt][nt][2] + xjB.x + xiB.x) * at0
                    + leakyr(D[tt][nt][3] + xjB.y + xiB.y) * at1;
            }
            pA += __shfl_xor_sync(0xFFFFFFFFu, pA, 1);
            pA += __shfl_xor_sync(0xFFFFFFFFu, pA, 2);
            pB += __shfl_xor_sync(0xFFFFFFFFu, pB, 1);
            pB += __shfl_xor_sync(0xFFFFFFFFu, pB, 2);
            if (c == 0) {
                if (vA) {
                    g_logits[(size_t)eeA * 4 + h] = pA;
                    atomicMaxF(&g_m1[(size_t)dA_ * 4 + h], pA);
                }
                if (vB) {
                    g_logits[(size_t)eeB * 4 + h] = pB;
                    atomicMaxF(&g_m1[(size_t)dB_ * 4 + h], pB);
                }
            }
        }
#pragma unroll
        for (int nt = 8; nt < 14; nt++) {
            int off = (nt < 12) ? (nt - 8) * 8 + c * 2
                                : 32 + (nt - 12) * 8 + c * 2;
            if (vA) *reinterpret_cast<float2*>(g_ea23 + (size_t)eeA * 48 + off) =
                        make_float2(D[tt][nt][0], D[tt][nt][1]);
            if (vB) *reinterpret_cast<float2*>(g_ea23 + (size_t)eeB * 48 + off) =
                        make_float2(D[tt][nt][2], D[tt][nt][3]);
        }
    }
}

// ---------------- softmax-exp + weighted aggregation (vector red) -----------
__global__ void k_soft1(const int* __restrict__ src, const int* __restrict__ dst, int e) {
    int t = blockIdx.x * blockDim.x + threadIdx.x;
    int ee = t >> 4;
    if (ee >= e) return;
    int q = t & 15, h = q >> 2, c4 = q * 4;
    int s = src[ee], d = dst[ee];
    float ex = expf(g_logits[(size_t)ee * 4 + h] - g_m1[(size_t)d * 4 + h]);
    if ((q & 3) == 0) atomicAdd(&g_s1[(size_t)d * 4 + h], ex);
    float4 x = *reinterpret_cast<const float4*>(g_xl + (size_t)s * 64 + c4);
    red4(g_num1 + (size_t)d * 64 + c4, ex * x.x, ex * x.y, ex * x.z, ex * x.w);
}

__global__ void k_soft2(const int* __restrict__ src, const int* __restrict__ dst, int e) {
    int t = blockIdx.x * blockDim.x + threadIdx.x;
    int ee = t >> 3;
    if (ee >= e) return;
    int q = t & 7, h = q >> 2, c4 = q * 4;
    int s = src[ee], d = dst[ee];
    float ex = expf(g_logits[(size_t)ee * 2 + h] - g_m2[(size_t)d * 2 + h]);
    if ((q & 3) == 0) atomicAdd(&g_s2[(size_t)d * 2 + h], ex);
    float4 x = *reinterpret_cast<const float4*>(g_xl + (size_t)s * 32 + c4);
    red4(g_num2 + (size_t)d * 32 + c4, ex * x.x, ex * x.y, ex * x.z, ex * x.w);
}

__global__ void k_soft3(const int* __restrict__ src, const int* __restrict__ dst, int e) {
    int t = blockIdx.x * blockDim.x + threadIdx.x;
    int ee = t >> 2;
    if (ee >= e) return;
    int q = t & 3, c4 = q * 4;
    int s = src[ee], d = dst[ee];
    float ex = expf(g_logits[ee] - g_m3[d]);
    if (q == 0) atomicAdd(&g_s3[d], ex);
    float4 x = *reinterpret_cast<const float4*>(g_xl + (size_t)s * 16 + c4);
    red4(g_num3 + (size_t)d * 16 + c4, ex * x.x, ex * x.y, ex * x.z, ex * x.w);
}

// ---------------- finish layer1 + project layer2 -----------------------------
__global__ void k_node_fin1(const float* __restrict__ bias1,
                            const float* __restrict__ Wl2, const float* __restrict__ bl2,
                            const float* __restrict__ Wr2, const float* __restrict__ br2,
                            int n) {
    int node = blockIdx.x;
    if (node >= n) return;
    int c = threadIdx.x;  // 0..63
    __shared__ float sx[64];
    float v = g_num1[(size_t)node * 64 + c] / (g_s1[(size_t)node * 4 + (c >> 4)] + 1e-16f) + bias1[c];
    sx[c] = eluf(v);
    __syncthreads();
    if (c < 32) {
        float a = bl2[c];
#pragma unroll
        for (int k = 0; k < 64; k++) a += sx[k] * Wl2[k * 32 + c];
        g_xl[(size_t)node * 32 + c] = a;
        g_num2[(size_t)node * 32 + c] = 0.f;
    } else {
        int c2 = c - 32;
        float a = br2[c2];
#pragma unroll
        for (int k = 0; k < 64; k++) a += sx[k] * Wr2[k * 32 + c2];
        g_xr[(size_t)node * 32 + c2] = a;
    }
    if (c < 2) { g_m2[(size_t)node * 2 + c] = -INFINITY; g_s2[(size_t)node * 2 + c] = 0.f; }
}

// ---------------- layer-2 logits ---------------------------------------------
__global__ void k_edge_logits2(const int* __restrict__ src, const int* __restrict__ dst,
                               const float* __restrict__ att2, int e) {
    int ee = blockIdx.x * 8 + (threadIdx.x >> 5);
    if (ee >= e) return;
    int c = threadIdx.x & 31;
    int s = src[ee], d = dst[ee];
    float ev = leakyr(g_xl[(size_t)s * 32 + c] + g_xr[(size_t)d * 32 + c] + g_ea23[(size_t)ee * 48 + c]);
    float p = ev * att2[c];
    p += __shfl_xor_sync(0xFFFFFFFFu, p, 8);
    p += __shfl_xor_sync(0xFFFFFFFFu, p, 4);
    p += __shfl_xor_sync(0xFFFFFFFFu, p, 2);
    p += __shfl_xor_sync(0xFFFFFFFFu, p, 1);
    if ((c & 15) == 0) {
        int h = c >> 4;
        g_logits[(size_t)ee * 2 + h] = p;
        atomicMaxF(&g_m2[(size_t)d * 2 + h], p);
    }
}

// ---------------- finish layer2 + project layer3 ------------------------------
__global__ void k_node_fin2(const float* __restrict__ bias2,
                            const float* __restrict__ Wl3, const float* __restrict__ bl3,
                            const float* __restrict__ Wr3, const float* __restrict__ br3,
                            int n) {
    int node = blockIdx.x;
    if (node >= n) return;
    int c = threadIdx.x;  // 0..31
    __shared__ float sx[32];
    float v = g_num2[(size_t)node * 32 + c] / (g_s2[(size_t)node * 2 + (c >> 4)] + 1e-16f) + bias2[c];
    sx[c] = eluf(v);
    __syncthreads();
    if (c < 16) {
        float a = bl3[c];
#pragma unroll
        for (int k = 0; k < 32; k++) a += sx[k] * Wl3[k * 16 + c];
        g_xl[(size_t)node * 16 + c] = a;
        g_num3[(size_t)node * 16 + c] = 0.f;
    } else {
        int c2 = c - 16;
        float a = br3[c2];
#pragma unroll
        for (int k = 0; k < 32; k++) a += sx[k] * Wr3[k * 16 + c2];
        g_xr[(size_t)node * 16 + c2] = a;
    }
    if (c == 0) { g_m3[node] = -INFINITY; g_s3[node] = 0.f; }
}

// ---------------- layer-3 logits ----------------------------------------------
__global__ void k_edge_logits3(const int* __restrict__ src, const int* __restrict__ dst,
                               const float* __restrict__ att3, int e) {
    int ee = blockIdx.x * 8 + (threadIdx.x >> 4);
    int c = threadIdx.x & 15;
    bool ok = ee < e;
    int s = ok ? src[ee] : 0, d = ok ? dst[ee] : 0;
    float ev = ok ? leakyr(g_xl[(size_t)s * 16 + c] + g_xr[(size_t)d * 16 + c] + g_ea23[(size_t)ee * 48 + 32 + c]) : 0.f;
    float p = ev * att3[c];
    p += __shfl_xor_sync(0xFFFFFFFFu, p, 8);
    p += __shfl_xor_sync(0xFFFFFFFFu, p, 4);
    p += __shfl_xor_sync(0xFFFFFFFFu, p, 2);
    p += __shfl_xor_sync(0xFFFFFFFFu, p, 1);
    if (ok && c == 0) {
        g_logits[ee] = p;
        atomicMaxF(&g_m3[d], p);
    }
}

// ---------------- finish layer3 ------------------------------------------------
__global__ void k_node_fin3(const float* __restrict__ bias3, int n) {
    int i = blockIdx.x * blockDim.x + threadIdx.x;
    if (i >= n * 16) return;
    g_x3[i] = g_num3[i] / (g_s3[i >> 4] + 1e-16f) + bias3[i & 15];
}

// ---------------- edge MLP: 8 edges per 128-thread block ----------------------
__global__ void k_mlp(const int* __restrict__ src, const int* __restrict__ dst,
                      const float* __restrict__ W1, const float* __restrict__ b1,
                      const float* __restrict__ W2, const float* __restrict__ b2,
                      const float* __restrict__ W3, const float* __restrict__ b3,
                      float* __restrict__ out, int e) {
    __shared__ float h0[8][32], h1[8][64], h2[8][32];
    int tid = threadIdx.x;
    int eb = blockIdx.x * 8;

    for (int i = tid; i < 256; i += 128) {
        int le = i >> 5, j = i & 31;
        int ee = eb + le;
        if (ee < e) {
            int nn = (j < 16) ? src[ee] : dst[ee];
            h0[le][j] = g_x3[(size_t)nn * 16 + (j & 15)];
        }
    }
    __syncthreads();

    {
        int j = tid & 63, g = tid >> 6;
        float a0 = b1[j], a1 = a0, a2 = a0, a3 = a0;
        const float* r0 = h0[g * 4 + 0];
        const float* r1 = h0[g * 4 + 1];
        const float* r2 = h0[g * 4 + 2];
        const float* r3 = h0[g * 4 + 3];
#pragma unroll
        for (int k = 0; k < 32; k++) {
            float w = W1[k * 64 + j];
            a0 += r0[k] * w; a1 += r1[k] * w; a2 += r2[k] * w; a3 += r3[k] * w;
        }
        h1[g * 4 + 0][j] = fmaxf(a0, 0.f);
        h1[g * 4 + 1][j] = fmaxf(a1, 0.f);
        h1[g * 4 + 2][j] = fmaxf(a2, 0.f);
        h1[g * 4 + 3][j] = fmaxf(a3, 0.f);
    }
    __syncthreads();

    {
        int j = tid & 31, g = tid >> 5;
        float a0 = b2[j], a1 = a0;
        const float* r0 = h1[g * 2 + 0];
        const float* r1 = h1[g * 2 + 1];
#pragma unroll
        for (int k = 0; k < 64; k++) {
            float w = W2[k * 32 + j];
            a0 += r0[k] * w; a1 += r1[k] * w;
        }
        h2[g * 2 + 0][j] = fmaxf(a0, 0.f);
        h2[g * 2 + 1][j] = fmaxf(a1, 0.f);
    }
    __syncthreads();

    {
        int e8 = tid >> 4, c = tid & 15;
        float p = h2[e8][c] * W3[c] + h2[e8][c + 16] * W3[c + 16];
        p += __shfl_xor_sync(0xFFFFFFFFu, p, 8);
        p += __shfl_xor_sync(0xFFFFFFFFu, p, 4);
        p += __shfl_xor_sync(0xFFFFFFFFu, p, 2);
        p += __shfl_xor_sync(0xFFFFFFFFu, p, 1);
        int ee = eb + e8;
        if (c == 0 && ee < e) out[ee] = p + b3[0];
    }
}

// ---------------- launch --------------------------------------------------------
extern "C" void kernel_launch(void* const* d_in, const int* in_sizes, int n_in,
                              void* d_out, int out_size) {
    const int*   node_ids = (const int*)  d_in[0];
    const int*   eidx     = (const int*)  d_in[1];
    const float* eattr    = (const float*)d_in[2];
    const float* emb      = (const float*)d_in[3];
    const float* l1_Wl   = (const float*)d_in[4];
    const float* l1_bl   = (const float*)d_in[5];
    const float* l1_Wr   = (const float*)d_in[6];
    const float* l1_br   = (const float*)d_in[7];
    const float* l1_We   = (const float*)d_in[8];
    const float* l1_att  = (const float*)d_in[9];
    const float* l1_bias = (const float*)d_in[10];
    const float* l2_Wl   = (const float*)d_in[11];
    const float* l2_bl   = (const float*)d_in[12];
    const float* l2_Wr   = (const float*)d_in[13];
    const float* l2_br   = (const float*)d_in[14];
    const float* l2_We   = (const float*)d_in[15];
    const float* l2_att  = (const float*)d_in[16];
    const float* l2_bias = (const float*)d_in[17];
    const float* l3_Wl   = (const float*)d_in[18];
    const float* l3_bl   = (const float*)d_in[19];
    const float* l3_Wr   = (const float*)d_in[20];
    const float* l3_br   = (const float*)d_in[21];
    const float* l3_We   = (const float*)d_in[22];
    const float* l3_att  = (const float*)d_in[23];
    const float* l3_bias = (const float*)d_in[24];
    const float* mlp_W1  = (const float*)d_in[25];
    const float* mlp_b1  = (const float*)d_in[26];
    const float* mlp_W2  = (const float*)d_in[27];
    const float* mlp_b2  = (const float*)d_in[28];
    const float* mlp_W3  = (const float*)d_in[29];
    const float* mlp_b3  = (const float*)d_in[30];

    int n = in_sizes[0];
    int e = in_sizes[1] / 2;
    const int* src = eidx;
    const int* dst = eidx + e;
    float* out = (float*)d_out;

    static bool attr_set = false;
    if (!attr_set) {
        cudaFuncSetAttribute(k_edge_mma, cudaFuncAttributeMaxDynamicSharedMemorySize, SM_EP_TOTAL);
        attr_set = true;
    }

    // ---- prep + layer 1 (edge GEMM is launch #4 for ncu visibility) ----
    k_prep_w<<<(NCOL * KPAD + 255) / 256, 256>>>(l1_We, l2_We, l3_We);
    k_node1<<<n, 64>>>(node_ids, emb, l1_Wl, l1_bl, l1_Wr, l1_br, n);
    k_init1<<<(n * 64 + 255) / 256, 256>>>(n);
    k_edge_mma<<<(e + 127) / 128, 128, SM_EP_TOTAL>>>(eattr, src, dst, l1_att, e);
    k_soft1<<<(e * 16 + 255) / 256, 256>>>(src, dst, e);
    k_node_fin1<<<n, 64>>>(l1_bias, l2_Wl, l2_bl, l2_Wr, l2_br, n);

    // ---- layer 2 ----
    k_edge_logits2<<<(e + 7) / 8, 256>>>(src, dst, l2_att, e);
    k_soft2<<<(e * 8 + 255) / 256, 256>>>(src, dst, e);
    k_node_fin2<<<n, 32>>>(l2_bias, l3_Wl, l3_bl, l3_Wr, l3_br, n);

    // ---- layer 3 ----
    k_edge_logits3<<<(e + 7) / 8, 128>>>(src, dst, l3_att, e);
    k_soft3<<<(e * 4 + 255) / 256, 256>>>(src, dst, e);
    k_node_fin3<<<(n * 16 + 255) / 256, 256>>>(l3_bias, n);

    // ---- edge MLP ----
    k_mlp<<<(e + 7) / 8, 128>>>(src, dst, mlp_W1, mlp_b1, mlp_W2, mlp_b2,
                                mlp_W3, mlp_b3, out, e);
}